// round 13
// baseline (speedup 1.0000x reference)
#include <cuda_runtime.h>
#include <cuda_fp16.h>

// ----------------------------------------------------------------------------
// SymplecticGyroceptron — R13: fp16 inner loop, 4 points/thread, TPB=128.
//
// Calibrated issue model: dur = instrs/neuron/2pt * 41.5us / issue_eff;
// floors fma=f*83us, tanh.f32=t*333us(rt8). R9: 12.3 instr @64% = 798.
// R12: 15 instr @73% = 857. This kernel: point-independent per-neuron costs
// (2 LDS + 2 ww-packs) amortized over 4 points -> 24 instr/neuron/4pt
// = 12.0/2pt with t=1 (tanh.f16x2, MUFU floor 333 not 665) and f=7.
//
// Shared per neuron (20B, LDS.128 + LDS.32, serves 4 pts = 5B/pt):
//   uint4: .x=h2(wx,wx) .y=h2(wy,wy) .z=h2(b,b) .w=f32 wwx
//   float: wwy
// wwx=-eps*wout*wx, wwy=-eps*wout*wy (negated: t^2-1 trick).
// Points: pair a=(pt0 lo, pt1 hi), pair b=(pt2, pt3); state packed u64.
// Geometry: TPB=128, launch_bounds(128,8), smem 20KB -> 8 CTAs/SM, grid 977.
// ----------------------------------------------------------------------------

#define NEUR 64
#define NLAYERS 16   // 0..7 = psi (eps=1), 8..15 = ni (eps=0.01)
#define TPB 128

typedef unsigned long long u64;
typedef unsigned int u32;

__device__ uint4  g_w[NLAYERS * NEUR];
__device__ float  g_wy[NLAYERS * NEUR];
__device__ float2 g_eta[NLAYERS];
__device__ float2 g_cs;

__device__ __forceinline__ u64 pack2(float lo, float hi) {
    u64 d; asm("mov.b64 %0, {%1, %2};" : "=l"(d) : "f"(lo), "f"(hi)); return d;
}
__device__ __forceinline__ void unpack2(u64 d, float& lo, float& hi) {
    asm("mov.b64 {%0, %1}, %2;" : "=f"(lo), "=f"(hi) : "l"(d));
}
__device__ __forceinline__ u64 ffma2(u64 a, u64 b, u64 c) {
    u64 d; asm("fma.rn.f32x2 %0, %1, %2, %3;" : "=l"(d) : "l"(a), "l"(b), "l"(c));
    return d;
}
__device__ __forceinline__ u64 fadd2(u64 a, u64 b) {
    u64 d; asm("add.rn.f32x2 %0, %1, %2;" : "=l"(d) : "l"(a), "l"(b));
    return d;
}
__device__ __forceinline__ u64 fmul2(u64 a, u64 b) {
    u64 d; asm("mul.rn.f32x2 %0, %1, %2;" : "=l"(d) : "l"(a), "l"(b));
    return d;
}
__device__ __forceinline__ u32 hfma2(u32 a, u32 b, u32 c) {
    u32 d; asm("fma.rn.f16x2 %0, %1, %2, %3;" : "=r"(d) : "r"(a), "r"(b), "r"(c));
    return d;
}
// u64 (f32 pair) -> f16x2, lo stays lo
__device__ __forceinline__ u32 cvt_h2(u64 p) {
    float lo, hi; unpack2(p, lo, hi);
    u32 d; asm("cvt.rn.f16x2.f32 %0, %1, %2;" : "=r"(d) : "f"(hi), "f"(lo));
    return d;
}
// f16x2 -> u64 (f32 pair)
__device__ __forceinline__ u64 cvt_f2(u32 h) {
    unsigned short lo, hi;
    asm("mov.b32 {%0, %1}, %2;" : "=h"(lo), "=h"(hi) : "r"(h));
    float fl, fh;
    asm("cvt.f32.f16 %0, %1;" : "=f"(fl) : "h"(lo));
    asm("cvt.f32.f16 %0, %1;" : "=f"(fh) : "h"(hi));
    return pack2(fl, fh);
}

__global__ void prep_kernel(const float* __restrict__ theta0,
                            const float* __restrict__ psi_Win,
                            const float* __restrict__ psi_Wout,
                            const float* __restrict__ psi_b,
                            const float* __restrict__ psi_eta,
                            const float* __restrict__ ni_Win,
                            const float* __restrict__ ni_Wout,
                            const float* __restrict__ ni_b,
                            const float* __restrict__ ni_eta)
{
    int t = threadIdx.x;
    if (t < NLAYERS * NEUR) {
        int l = t >> 6;
        int j = t & 63;
        const float *Win, *Wout, *b;
        float eps;
        int i;
        if (l < 8) { i = l;     Win = psi_Win; Wout = psi_Wout; b = psi_b; eps = 1.0f;  }
        else       { i = l - 8; Win = ni_Win;  Wout = ni_Wout;  b = ni_b;  eps = 0.01f; }
        float w0 = Win[i * 128 + j];        // W_in[i][0][j]
        float w1 = Win[i * 128 + 64 + j];   // W_in[i][1][j]
        float bb = b[i * 64 + j];           // b_in[i][0][j]
        float wo = -Wout[i * 64 + j] * eps; // NEGATED eps*W_out (t^2-1 trick)

        u32 hx = (u32)__half_as_ushort(__float2half_rn(w0));
        u32 hy = (u32)__half_as_ushort(__float2half_rn(w1));
        u32 hb = (u32)__half_as_ushort(__float2half_rn(bb));
        uint4 w;
        w.x = (hx << 16) | hx;              // h2(wx, wx)
        w.y = (hy << 16) | hy;              // h2(wy, wy)
        w.z = (hb << 16) | hb;              // h2(b, b)
        w.w = __float_as_uint(wo * w0);     // f32 wwx
        g_w[t]  = w;
        g_wy[t] = wo * w1;                  // f32 wwy
    }
    if (t < NLAYERS) {
        const float* e = (t < 8) ? (psi_eta + t * 2) : (ni_eta + (t - 8) * 2);
        g_eta[t] = make_float2(e[0], e[1]);
    }
    if (t == 0) {
        float th = theta0[0];
        g_cs = make_float2(cosf(th), sinf(th));
    }
}

// grad_V for 4 points: packed pairs a=(pt0,pt1), b=(pt2,pt3).
// Y inputs are f32 pairs; converted to h2 once per call.
__device__ __forceinline__ void grad4(const uint4* __restrict__ sw,
                                      const float* __restrict__ swy,
                                      u64 Y0a, u64 Y1a, u64 Y0b, u64 Y1b,
                                      u64& G0a, u64& G1a, u64& G0b, u64& G1b)
{
    const u32 NEG1H = 0xBC00BC00u;   // h2(-1, -1)
    u32 Y0ha = cvt_h2(Y0a), Y1ha = cvt_h2(Y1a);
    u32 Y0hb = cvt_h2(Y0b), Y1hb = cvt_h2(Y1b);

    u64 acc0a = 0ull, acc1a = 0ull, acc0b = 0ull, acc1b = 0ull;
#pragma unroll 2
    for (int j = 0; j < NEUR; ++j) {
        uint4 w  = sw[j];
        float wwy = swy[j];
        float wwx = __uint_as_float(w.w);
        u64 WX = pack2(wwx, wwx);
        u64 WY = pack2(wwy, wwy);
        // pair a
        {
            u32 p = hfma2(Y0ha, w.x, hfma2(Y1ha, w.y, w.z));
            u32 th; asm("tanh.approx.f16x2 %0, %1;" : "=r"(th) : "r"(p));
            u32 m = hfma2(th, th, NEG1H);           // t^2 - 1 (fp16)
            u64 M = cvt_f2(m);
            acc0a = ffma2(M, WX, acc0a);
            acc1a = ffma2(M, WY, acc1a);
        }
        // pair b
        {
            u32 p = hfma2(Y0hb, w.x, hfma2(Y1hb, w.y, w.z));
            u32 th; asm("tanh.approx.f16x2 %0, %1;" : "=r"(th) : "r"(p));
            u32 m = hfma2(th, th, NEG1H);
            u64 M = cvt_f2(m);
            acc0b = ffma2(M, WX, acc0b);
            acc1b = ffma2(M, WY, acc1b);
        }
    }
    G0a = acc0a; G1a = acc1a; G0b = acc0b; G1b = acc1b;
}

__global__ void __launch_bounds__(TPB, 8)
gyro_kernel(const float4* __restrict__ rin, float4* __restrict__ out,
            int B, int q)
{
    __shared__ uint4  sw [NLAYERS * NEUR];
    __shared__ float  swy[NLAYERS * NEUR];
    __shared__ float2 seta[NLAYERS];
    __shared__ float2 scs;

    for (int i = threadIdx.x; i < NLAYERS * NEUR; i += TPB) {
        sw[i]  = g_w[i];
        swy[i] = g_wy[i];
    }
    if (threadIdx.x < NLAYERS) seta[threadIdx.x] = g_eta[threadIdx.x];
    if (threadIdx.x == 0)      scs = g_cs;
    __syncthreads();

    int idx = blockIdx.x * TPB + threadIdx.x;
    if (idx >= q) return;
    int i1 = idx + q, i2 = idx + 2 * q, i3 = idx + 3 * q;
    bool h1 = i1 < B, h2 = i2 < B, h3 = i3 < B;
    int c1 = h1 ? i1 : idx, c2 = h2 ? i2 : idx, c3 = h3 ? i3 : idx;

    const u64 NEG1 = pack2(-1.0f, -1.0f);

    float4 z0 = rin[idx];
    float4 z1 = rin[c1];
    float4 z2 = rin[c2];
    float4 z3 = rin[c3];
    u64 X0a = pack2(z0.x, z1.x), X1a = pack2(z0.y, z1.y);
    u64 Y0a = pack2(z0.z, z1.z), Y1a = pack2(z0.w, z1.w);
    u64 X0b = pack2(z2.x, z3.x), X1b = pack2(z2.y, z3.y);
    u64 Y0b = pack2(z2.z, z3.z), Y1b = pack2(z2.w, z3.w);

    // ---- inverse psi layers, l = 7 .. 0 ----
    for (int l = 7; l >= 0; --l) {
        u64 nE0 = pack2(-seta[l].x, -seta[l].x);
        u64 nE1 = pack2(-seta[l].y, -seta[l].y);
        const uint4* w  = &sw [l * NEUR];
        const float* wy = &swy[l * NEUR];
#pragma unroll 1
        for (int k = 0; k < 4; ++k) {
            u64 Yn0a = fadd2(X0a, nE0), Yn1a = fadd2(X1a, nE1);
            u64 Yn0b = fadd2(X0b, nE0), Yn1b = fadd2(X1b, nE1);
            u64 G0a, G1a, G0b, G1b;
            grad4(w, wy, Yn0a, Yn1a, Yn0b, Yn1b, G0a, G1a, G0b, G1b);
            u64 Nx0a = ffma2(Y0a, NEG1, G0a);   // G - Y
            u64 Nx1a = ffma2(Y1a, NEG1, G1a);
            u64 Nx0b = ffma2(Y0b, NEG1, G0b);
            u64 Nx1b = ffma2(Y1b, NEG1, G1b);
            Y0a = Yn0a; Y1a = Yn1a; X0a = Nx0a; X1a = Nx1a;
            Y0b = Yn0b; Y1b = Yn1b; X0b = Nx0b; X1b = Nx1b;
        }
    }

    // ---- circle action (q1 = X0, p1 = Y0) ----
    {
        u64 C  = pack2(scs.x,  scs.x);
        u64 S  = pack2(scs.y,  scs.y);
        u64 nS = pack2(-scs.y, -scs.y);
        u64 qa = X0a, pa = Y0a;
        X0a = ffma2(C, qa, fmul2(S,  pa));
        Y0a = ffma2(C, pa, fmul2(nS, qa));
        u64 qb = X0b, pb = Y0b;
        X0b = ffma2(C, qb, fmul2(S,  pb));
        Y0b = ffma2(C, pb, fmul2(nS, qb));
    }

    // ---- forward layers: l = 0..7 psi, l = 8..15 ni ----
    for (int l = 0; l < NLAYERS; ++l) {
        u64 E0 = pack2(seta[l].x, seta[l].x);
        u64 E1 = pack2(seta[l].y, seta[l].y);
        const uint4* w  = &sw [l * NEUR];
        const float* wy = &swy[l * NEUR];
#pragma unroll 1
        for (int k = 0; k < 4; ++k) {
            u64 G0a, G1a, G0b, G1b;
            grad4(w, wy, Y0a, Y1a, Y0b, Y1b, G0a, G1a, G0b, G1b);
            u64 Nx0a = fadd2(Y0a, E0), Nx1a = fadd2(Y1a, E1);
            u64 Ny0a = ffma2(X0a, NEG1, G0a), Ny1a = ffma2(X1a, NEG1, G1a);
            u64 Nx0b = fadd2(Y0b, E0), Nx1b = fadd2(Y1b, E1);
            u64 Ny0b = ffma2(X0b, NEG1, G0b), Ny1b = ffma2(X1b, NEG1, G1b);
            X0a = Nx0a; X1a = Nx1a; Y0a = Ny0a; Y1a = Ny1a;
            X0b = Nx0b; X1b = Nx1b; Y0b = Ny0b; Y1b = Ny1b;
        }
    }

    float p0x0, p1x0, p0x1, p1x1, p0y0, p1y0, p0y1, p1y1;
    unpack2(X0a, p0x0, p1x0); unpack2(X1a, p0x1, p1x1);
    unpack2(Y0a, p0y0, p1y0); unpack2(Y1a, p0y1, p1y1);
    float p2x0, p3x0, p2x1, p3x1, p2y0, p3y0, p2y1, p3y1;
    unpack2(X0b, p2x0, p3x0); unpack2(X1b, p2x1, p3x1);
    unpack2(Y0b, p2y0, p3y0); unpack2(Y1b, p2y1, p3y1);

    out[idx] = make_float4(p0x0, p0x1, p0y0, p0y1);
    if (h1) out[i1] = make_float4(p1x0, p1x1, p1y0, p1y1);
    if (h2) out[i2] = make_float4(p2x0, p2x1, p2y0, p2y1);
    if (h3) out[i3] = make_float4(p3x0, p3x1, p3y0, p3y1);
}

extern "C" void kernel_launch(void* const* d_in, const int* in_sizes, int n_in,
                              void* d_out, int out_size)
{
    const float* r        = (const float*)d_in[0];
    const float* theta0   = (const float*)d_in[1];
    const float* psi_Win  = (const float*)d_in[2];
    const float* psi_Wout = (const float*)d_in[3];
    const float* psi_b    = (const float*)d_in[4];
    const float* psi_eta  = (const float*)d_in[5];
    const float* ni_Win   = (const float*)d_in[6];
    const float* ni_Wout  = (const float*)d_in[7];
    const float* ni_b     = (const float*)d_in[8];
    const float* ni_eta   = (const float*)d_in[9];

    int B = in_sizes[0] / 4;
    int q = (B + 3) / 4;

    prep_kernel<<<1, 1024>>>(theta0, psi_Win, psi_Wout, psi_b, psi_eta,
                             ni_Win, ni_Wout, ni_b, ni_eta);

    int blocks = (q + TPB - 1) / TPB;
    gyro_kernel<<<blocks, TPB>>>((const float4*)r, (float4*)d_out, B, q);
}

// round 14
// speedup vs baseline: 1.1114x; 1.1114x over previous
#include <cuda_runtime.h>
#include <cuda_fp16.h>

// ----------------------------------------------------------------------------
// SymplecticGyroceptron — R14: tensor-core grad_V (back-to-back mma).
//
// Per warp: 32 points. Per substep:
//   GEMM1: pre[32x64] = A1[32x8] * B1[8x64]   (A rows = points; k0,k1 = y0,y1;
//          k2 = 1.0 -> bias folded into B row k2; k3-7 = 0)
//          8 n-tiles x 2 m-tiles = 16 x mma.m16n8k8.f32.f16.f16.f32
//   elementwise (on C fragments, layout-agnostic):
//          h = cvt f32x2->f16x2 ; t = tanh.approx.f16x2 ; m = t*t - 1 (HFMA2)
//   GEMM2: G[32x8] = M[32x64] * Wg[64x8]  (cols 0,1 = -eps*wout*win x/y, rest 0)
//          Wg split-precision: hi = f16(Wg), lo = f16(Wg - hi) -> 2 mma each
//          4 k-tiles x 2 m-tiles x 2 splits = 16 x mma.m16n8k16
//   KEY: C-fragment(m16n8, f16 pair) == A-fragment(m16n8k16) -> zero shuffles.
//
// State (x0,x1,y0,y1 f32) lives ONLY in lanes with lane%4==0 (8 lanes x 4 pts:
// rows r, r+8, r+16, r+24, r = lane/4) — exactly the rows those lanes own in
// both the A1 fragment (k0,k1) and the C2 fragment (n0,n1). Lanes lane%4==1
// supply the constant bias row h2(1,0); lanes 2,3 supply zeros.
//
// Floors: MUFU (tanh) 333us [binding], tensor ~250, fma ~210, issue ~200.
// ----------------------------------------------------------------------------

#define NLAYERS 16   // 0..7 = psi (eps=1), 8..15 = ni (eps=0.01)
#define TPB 128

typedef unsigned int u32;

__device__ u32    g_B1[NLAYERS * 8 * 16];          // [l][j(ntile)][idx=q*8+c]
__device__ u32    g_Bg[NLAYERS * 4 * 2 * 2 * 8];   // [l][kt][s(hi/lo)][rr(b0/b1)][idx2=q*2+nn]
__device__ float2 g_eta[NLAYERS];
__device__ float2 g_cs;

__device__ __forceinline__ u32 f2h2(float lo, float hi) {
    u32 d; asm("cvt.rn.f16x2.f32 %0, %1, %2;" : "=r"(d) : "f"(hi), "f"(lo));
    return d;   // lo operand -> low half (element 0)
}

__global__ void prep_kernel(const float* __restrict__ theta0,
                            const float* __restrict__ psi_Win,
                            const float* __restrict__ psi_Wout,
                            const float* __restrict__ psi_b,
                            const float* __restrict__ psi_eta,
                            const float* __restrict__ ni_Win,
                            const float* __restrict__ ni_Wout,
                            const float* __restrict__ ni_b,
                            const float* __restrict__ ni_eta)
{
    int t = threadIdx.x;

    // ---- B1 table (GEMM1 B fragments): 2048 entries ----
    for (int e = t; e < NLAYERS * 8 * 16; e += blockDim.x) {
        int l = e >> 7;
        int rem = e & 127;
        int j = rem >> 4, idx = rem & 15;
        int q = idx >> 3, c = idx & 7;   // q = lane%4 class (0/1), c = col lane/4
        int n = j * 8 + c;
        const float *Win, *b; int i;
        if (l < 8) { i = l;     Win = psi_Win; b = psi_b; }
        else       { i = l - 8; Win = ni_Win;  b = ni_b;  }
        float wx = Win[i * 128 + n];
        float wy = Win[i * 128 + 64 + n];
        float bb = b[i * 64 + n];
        u32 v;
        if (q == 0) {   // k0,k1 = (wx, wy)
            u32 hx = (u32)__half_as_ushort(__float2half_rn(wx));
            u32 hy = (u32)__half_as_ushort(__float2half_rn(wy));
            v = (hy << 16) | hx;
        } else {        // k2,k3 = (b, 0)
            v = (u32)__half_as_ushort(__float2half_rn(bb));
        }
        g_B1[e] = v;
    }

    // ---- Bg table (GEMM2 B fragments, split hi/lo): 4096 entries ----
    for (int e = t; e < NLAYERS * 4 * 2 * 2 * 8; e += blockDim.x) {
        int idx2 = e & 7;
        int rr = (e >> 3) & 1;
        int s  = (e >> 4) & 1;
        int kt = (e >> 5) & 3;
        int l  = e >> 7;
        int q = idx2 >> 1, nn = idx2 & 1;      // q = lane%4, nn = col (0=wwx,1=wwy)
        int k = kt * 16 + rr * 8 + q * 2;      // neuron index (k) and k+1
        const float *Win, *Wout; float eps; int i;
        if (l < 8) { i = l;     Win = psi_Win; Wout = psi_Wout; eps = 1.0f;  }
        else       { i = l - 8; Win = ni_Win;  Wout = ni_Wout;  eps = 0.01f; }
        float w0 = Win[i * 128 + (nn ? 64 : 0) + k];
        float w1 = Win[i * 128 + (nn ? 64 : 0) + k + 1];
        float v0 = -Wout[i * 64 + k]     * eps * w0;   // negated: t^2-1 trick
        float v1 = -Wout[i * 64 + k + 1] * eps * w1;
        __half h0 = __float2half_rn(v0), h1 = __float2half_rn(v1);
        if (s == 1) {   // residual (split precision)
            h0 = __float2half_rn(v0 - __half2float(h0));
            h1 = __float2half_rn(v1 - __half2float(h1));
        }
        g_Bg[e] = ((u32)__half_as_ushort(h1) << 16) | (u32)__half_as_ushort(h0);
    }

    if (t < NLAYERS) {
        const float* e2 = (t < 8) ? (psi_eta + t * 2) : (ni_eta + (t - 8) * 2);
        g_eta[t] = make_float2(e2[0], e2[1]);
    }
    if (t == 0) {
        float th = theta0[0];
        g_cs = make_float2(cosf(th), sinf(th));
    }
}

struct Frags {
    u32 B1[8];
    u32 Bg[4][2][2];   // [kt][s][rr]
};

__device__ __forceinline__ void load_frags(Frags& F, const u32* sB1, const u32* sBg,
                                           int l, int lane)
{
    int q = lane & 3, c = lane >> 2;
    bool hasB1 = (q < 2);
    int i1 = (l * 8) * 16 + q * 8 + c;
#pragma unroll
    for (int j = 0; j < 8; ++j)
        F.B1[j] = hasB1 ? sB1[i1 + j * 16] : 0u;
    bool hasBg = (c < 2);
    int idx2 = q * 2 + c;   // valid only when c<2
#pragma unroll
    for (int kt = 0; kt < 4; ++kt)
#pragma unroll
        for (int s = 0; s < 2; ++s)
#pragma unroll
            for (int rr = 0; rr < 2; ++rr)
                F.Bg[kt][s][rr] =
                    hasBg ? sBg[((((l * 4 + kt) * 2 + s) * 2 + rr) * 8) + idx2] : 0u;
}

// grad_V for 32 points via back-to-back mma. yn/G indexed: i -> row
// (i>>1)*16 + lane/4 + (i&1)*8  == points {r, r+8, r+16, r+24}.
__device__ __forceinline__ void grad_mma(const Frags& F,
                                         const float yn0[4], const float yn1[4],
                                         bool own, u32 aconst,
                                         float G0[4], float G1[4])
{
    u32 A1[2][2];
#pragma unroll
    for (int mt = 0; mt < 2; ++mt) {
        u32 v0 = f2h2(yn0[2 * mt],     yn1[2 * mt]);
        u32 v1 = f2h2(yn0[2 * mt + 1], yn1[2 * mt + 1]);
        A1[mt][0] = own ? v0 : aconst;
        A1[mt][1] = own ? v1 : aconst;
    }
    float C2[2][4] = {{0.f,0.f,0.f,0.f},{0.f,0.f,0.f,0.f}};
    const u32 NEG1H = 0xBC00BC00u;   // h2(-1,-1)
#pragma unroll
    for (int kt = 0; kt < 4; ++kt) {
        u32 A2[2][4];
#pragma unroll
        for (int jj = 0; jj < 2; ++jj) {
            u32 b1 = F.B1[kt * 2 + jj];
#pragma unroll
            for (int mt = 0; mt < 2; ++mt) {
                float c0 = 0.f, c1 = 0.f, c2 = 0.f, c3 = 0.f;
                asm("mma.sync.aligned.m16n8k8.row.col.f32.f16.f16.f32 "
                    "{%0,%1,%2,%3}, {%4,%5}, {%6}, {%0,%1,%2,%3};"
                    : "+f"(c0), "+f"(c1), "+f"(c2), "+f"(c3)
                    : "r"(A1[mt][0]), "r"(A1[mt][1]), "r"(b1));
                u32 h0 = f2h2(c0, c1);     // (row,   n, n+1)
                u32 h1 = f2h2(c2, c3);     // (row+8, n, n+1)
                asm("tanh.approx.f16x2 %0, %0;" : "+r"(h0));
                asm("tanh.approx.f16x2 %0, %0;" : "+r"(h1));
                u32 m0, m1;
                asm("fma.rn.f16x2 %0, %1, %1, %2;" : "=r"(m0) : "r"(h0), "r"(NEG1H));
                asm("fma.rn.f16x2 %0, %1, %1, %2;" : "=r"(m1) : "r"(h1), "r"(NEG1H));
                A2[mt][jj * 2]     = m0;   // C-frag == A-frag identity
                A2[mt][jj * 2 + 1] = m1;
            }
        }
#pragma unroll
        for (int mt = 0; mt < 2; ++mt)
#pragma unroll
            for (int s = 0; s < 2; ++s) {
                asm("mma.sync.aligned.m16n8k16.row.col.f32.f16.f16.f32 "
                    "{%0,%1,%2,%3}, {%4,%5,%6,%7}, {%8,%9}, {%0,%1,%2,%3};"
                    : "+f"(C2[mt][0]), "+f"(C2[mt][1]),
                      "+f"(C2[mt][2]), "+f"(C2[mt][3])
                    : "r"(A2[mt][0]), "r"(A2[mt][1]), "r"(A2[mt][2]), "r"(A2[mt][3]),
                      "r"(F.Bg[kt][s][0]), "r"(F.Bg[kt][s][1]));
            }
    }
#pragma unroll
    for (int mt = 0; mt < 2; ++mt) {
        G0[2 * mt]     = C2[mt][0];   // (row,   n=0) = g0
        G1[2 * mt]     = C2[mt][1];   // (row,   n=1) = g1
        G0[2 * mt + 1] = C2[mt][2];   // (row+8, n=0)
        G1[2 * mt + 1] = C2[mt][3];
    }
}

__global__ void __launch_bounds__(TPB, 4)
gyro_kernel(const float4* __restrict__ rin, float4* __restrict__ out,
            int B, int nWarps)
{
    __shared__ u32    sB1[NLAYERS * 8 * 16];
    __shared__ u32    sBg[NLAYERS * 4 * 2 * 2 * 8];
    __shared__ float2 seta[NLAYERS];
    __shared__ float2 scs;

    for (int i = threadIdx.x; i < NLAYERS * 8 * 16; i += TPB)       sB1[i] = g_B1[i];
    for (int i = threadIdx.x; i < NLAYERS * 4 * 2 * 2 * 8; i += TPB) sBg[i] = g_Bg[i];
    if (threadIdx.x < NLAYERS) seta[threadIdx.x] = g_eta[threadIdx.x];
    if (threadIdx.x == 0)      scs = g_cs;
    __syncthreads();

    int wid = blockIdx.x * (TPB / 32) + (threadIdx.x >> 5);
    if (wid >= nWarps) return;
    int lane = threadIdx.x & 31;
    int base = wid * 32;
    int r = lane >> 2;
    bool own = (lane & 3) == 0;
    u32 aconst = ((lane & 3) == 1) ? 0x00003C00u : 0u;   // h2(1,0) bias row

    int pidx[4] = { base + r, base + r + 8, base + r + 16, base + r + 24 };
    float x0[4] = {0,0,0,0}, x1[4] = {0,0,0,0};
    float y0[4] = {0,0,0,0}, y1[4] = {0,0,0,0};
    if (own) {
#pragma unroll
        for (int i = 0; i < 4; ++i) if (pidx[i] < B) {
            float4 z = rin[pidx[i]];
            x0[i] = z.x; x1[i] = z.y; y0[i] = z.z; y1[i] = z.w;
        }
    }

    Frags F;

    // ---- inverse psi layers, l = 7 .. 0 ----
    for (int l = 7; l >= 0; --l) {
        load_frags(F, sB1, sBg, l, lane);
        float e0 = seta[l].x, e1 = seta[l].y;
#pragma unroll 1
        for (int k = 0; k < 4; ++k) {
            float yn0[4], yn1[4], G0[4], G1[4];
#pragma unroll
            for (int i = 0; i < 4; ++i) { yn0[i] = x0[i] - e0; yn1[i] = x1[i] - e1; }
            grad_mma(F, yn0, yn1, own, aconst, G0, G1);
#pragma unroll
            for (int i = 0; i < 4; ++i) {
                float nx0 = G0[i] - y0[i], nx1 = G1[i] - y1[i];
                y0[i] = yn0[i]; y1[i] = yn1[i];
                x0[i] = nx0;    x1[i] = nx1;
            }
        }
    }

    // ---- circle action ----
    {
        float c = scs.x, s = scs.y;
#pragma unroll
        for (int i = 0; i < 4; ++i) {
            float q1 = x0[i], p1 = y0[i];
            x0[i] = fmaf(c, q1, s * p1);
            y0[i] = fmaf(c, p1, -s * q1);
        }
    }

    // ---- forward layers: l = 0..7 psi, l = 8..15 ni ----
    for (int l = 0; l < NLAYERS; ++l) {
        load_frags(F, sB1, sBg, l, lane);
        float e0 = seta[l].x, e1 = seta[l].y;
#pragma unroll 1
        for (int k = 0; k < 4; ++k) {
            float G0[4], G1[4];
            grad_mma(F, y0, y1, own, aconst, G0, G1);
#pragma unroll
            for (int i = 0; i < 4; ++i) {
                float nx0 = y0[i] + e0, nx1 = y1[i] + e1;
                float ny0 = G0[i] - x0[i], ny1 = G1[i] - x1[i];
                x0[i] = nx0; x1[i] = nx1;
                y0[i] = ny0; y1[i] = ny1;
            }
        }
    }

    if (own) {
#pragma unroll
        for (int i = 0; i < 4; ++i) if (pidx[i] < B)
            out[pidx[i]] = make_float4(x0[i], x1[i], y0[i], y1[i]);
    }
}

extern "C" void kernel_launch(void* const* d_in, const int* in_sizes, int n_in,
                              void* d_out, int out_size)
{
    const float* r        = (const float*)d_in[0];
    const float* theta0   = (const float*)d_in[1];
    const float* psi_Win  = (const float*)d_in[2];
    const float* psi_Wout = (const float*)d_in[3];
    const float* psi_b    = (const float*)d_in[4];
    const float* psi_eta  = (const float*)d_in[5];
    const float* ni_Win   = (const float*)d_in[6];
    const float* ni_Wout  = (const float*)d_in[7];
    const float* ni_b     = (const float*)d_in[8];
    const float* ni_eta   = (const float*)d_in[9];

    int B = in_sizes[0] / 4;
    int nWarps = (B + 31) / 32;

    prep_kernel<<<1, 1024>>>(theta0, psi_Win, psi_Wout, psi_b, psi_eta,
                             ni_Win, ni_Wout, ni_b, ni_eta);

    int blocks = (nWarps + (TPB / 32) - 1) / (TPB / 32);
    gyro_kernel<<<blocks, TPB>>>((const float4*)r, (float4*)d_out, B, nWarps);
}